// round 14
// baseline (speedup 1.0000x reference)
#include <cuda_runtime.h>
#include <cuda_bf16.h>

// Problem constants (match reference)
#define B_SZ       128
#define S_SZ       4096
#define TOK        64          // token_dim
#define EFF        60          // token_dim - 4
#define NF         20          // num features
#define H0         256
#define H1         128
#define H2         64
#define OUT        3
#define CHUNKS     4
#define CHUNK_S    (S_SZ / CHUNKS)   // 1024 tokens per chunk

// Scratch: partial column sums per (batch, chunk): [B, CHUNKS, TOK]
__device__ float g_partial[B_SZ * CHUNKS * TOK];
// Per-batch arrival counters. Zero at module load; the elected block resets
// its own counter every launch, so graph replays always start from zero.
__device__ int g_count[B_SZ];

// ---------------------------------------------------------------------------
// Fused kernel: R1's proven streaming geometry (512 blocks x 256 threads,
// ~6.8 TB/s) + threadFenceReduction election; the last block to finish a
// batch runs that batch's MLP immediately (overlapping other batches'
// still-streaming blocks). 8-warp MLP with interleaved shfl chains.
// ---------------------------------------------------------------------------
__global__ __launch_bounds__(256, 4)
void fused_kernel(const float* __restrict__ x,
                  const float* __restrict__ w_ext, const float* __restrict__ b_ext,
                  const float* __restrict__ w0, const float* __restrict__ b0,
                  const float* __restrict__ w1, const float* __restrict__ b1,
                  const float* __restrict__ w2, const float* __restrict__ b2,
                  const float* __restrict__ w3, const float* __restrict__ b3,
                  float* __restrict__ out) {
    const int b = blockIdx.x >> 2;        // batch
    const int c = blockIdx.x & 3;         // chunk
    const int t = threadIdx.x;            // 0..255
    const int w = t >> 5;                 // warp 0..7
    const int lane = t & 31;

    __shared__ float4 sm[256];            // stream reduction buffer (4 KB)
    __shared__ float xm[TOK];
    __shared__ float feats[NF];
    __shared__ float a0[H0];
    __shared__ float a1[H1];
    __shared__ float a2[H2];
    __shared__ int s_elect;

    // ---------------- Phase 1: streaming column sum over this chunk --------
    {
        const float4* __restrict__ p =
            (const float4*)(x + ((size_t)b * S_SZ + (size_t)c * CHUNK_S) * TOK);
        // 16384 float4 per block; 64 per thread. Stride 256 (mult of 16)
        // keeps each thread on one float4 column-group.
        float4 acc = make_float4(0.f, 0.f, 0.f, 0.f);
        #pragma unroll 16
        for (int i = t; i < CHUNK_S * (TOK / 4); i += 256) {
            float4 v = __ldcs(&p[i]);     // streaming: x touched exactly once
            acc.x += v.x; acc.y += v.y; acc.z += v.z; acc.w += v.w;
        }
        sm[t] = acc;
        __syncthreads();

        if (t < 16) {
            float4 s = make_float4(0.f, 0.f, 0.f, 0.f);
            #pragma unroll
            for (int k = 0; k < 16; k++) {
                float4 v = sm[t + k * 16];
                s.x += v.x; s.y += v.y; s.z += v.z; s.w += v.w;
            }
            float* dst = &g_partial[(size_t)(b * CHUNKS + c) * TOK + t * 4];
            dst[0] = s.x; dst[1] = s.y; dst[2] = s.z; dst[3] = s.w;
        }
    }

    // ---------------- Election (canonical threadFenceReduction) ------------
    __threadfence();                      // publish partials (storing threads)
    __syncthreads();                      // t0 waits for storers' fences
    if (t == 0) {
        int old = atomicAdd(&g_count[b], 1);
        int e = (old == CHUNKS - 1);
        if (e) g_count[b] = 0;            // reset for next launch/replay
        s_elect = e;
    }
    __syncthreads();
    if (!s_elect) return;
    __threadfence();                      // acquire: see other blocks' partials

    // ---------------- Phase 2: per-batch MLP (8 warps) ---------------------
    // Combine chunk partials -> mean
    if (t < TOK) {
        const float* p0 = &g_partial[(size_t)(b * CHUNKS) * TOK + t];
        float s = (p0[0] + p0[TOK]) + (p0[2 * TOK] + p0[3 * TOK]);
        xm[t] = s * (1.0f / (float)S_SZ);
    }
    __syncthreads();

    // Extractor: 20 neurons. Warp w does j = w + 8r, r=0..2 (guard j<20).
    {
        float s[3];
        #pragma unroll
        for (int r = 0; r < 3; r++) {
            const int j = w + r * 8;
            s[r] = 0.f;
            if (j < NF && lane < 15) {
                const float4 wv = ((const float4*)(w_ext + j * EFF))[lane];
                const float4 av = ((const float4*)xm)[lane];
                s[r] = fmaf(av.x, wv.x, fmaf(av.y, wv.y,
                       fmaf(av.z, wv.z, av.w * wv.w)));
            }
        }
        #pragma unroll
        for (int d = 1; d <= 16; d <<= 1) {
            #pragma unroll
            for (int r = 0; r < 3; r++)
                s[r] += __shfl_xor_sync(0xFFFFFFFF, s[r], d);
        }
        if (lane == 0) {
            #pragma unroll
            for (int r = 0; r < 3; r++) {
                const int j = w + r * 8;
                if (j < NF) feats[j] = s[r] + b_ext[j];
            }
        }
    }
    __syncthreads();

    // Layer 0: 20 -> 256 + ReLU. One neuron per thread.
    {
        const float* __restrict__ wp = w0 + t * NF;
        float s0 = b0[t], s1 = 0.f;
        #pragma unroll
        for (int k = 0; k < NF; k += 2) {
            s0 = fmaf(feats[k + 0], wp[k + 0], s0);
            s1 = fmaf(feats[k + 1], wp[k + 1], s1);
        }
        a0[t] = fmaxf(s0 + s1, 0.f);
    }
    __syncthreads();

    // Layer 1: 256 -> 128 + ReLU. Warp w: neurons j = w + 8m, m=0..15,
    // processed as 4 groups of 4 interleaved (independent) chains.
    {
        const float4* ar = (const float4*)a0;
        const float4 a0v = ar[lane];
        const float4 a1v = ar[lane + 32];
        #pragma unroll
        for (int g = 0; g < 4; g++) {
            float s[4];
            #pragma unroll
            for (int k = 0; k < 4; k++) {
                const int j = w + 8 * (g * 4 + k);
                const float4* wr = (const float4*)(w1 + j * H0);
                const float4 wva = wr[lane];
                const float4 wvb = wr[lane + 32];
                float p0 = fmaf(a0v.x, wva.x, a0v.y * wva.y);
                float p1 = fmaf(a0v.z, wva.z, a0v.w * wva.w);
                float p2 = fmaf(a1v.x, wvb.x, a1v.y * wvb.y);
                float p3 = fmaf(a1v.z, wvb.z, a1v.w * wvb.w);
                s[k] = (p0 + p1) + (p2 + p3);
            }
            #pragma unroll
            for (int d = 1; d <= 16; d <<= 1) {
                #pragma unroll
                for (int k = 0; k < 4; k++)
                    s[k] += __shfl_xor_sync(0xFFFFFFFF, s[k], d);
            }
            if (lane == 0) {
                #pragma unroll
                for (int k = 0; k < 4; k++) {
                    const int j = w + 8 * (g * 4 + k);
                    a1[j] = fmaxf(s[k] + b1[j], 0.f);
                }
            }
        }
    }
    __syncthreads();

    // Layer 2: 128 -> 64 + ReLU. Warp w: neurons j = w + 8m, m=0..7,
    // as 2 groups of 4 interleaved chains.
    {
        const float4 av = ((const float4*)a1)[lane];
        #pragma unroll
        for (int g = 0; g < 2; g++) {
            float s[4];
            #pragma unroll
            for (int k = 0; k < 4; k++) {
                const int j = w + 8 * (g * 4 + k);
                const float4 wv = ((const float4*)(w2 + j * H1))[lane];
                float p0 = fmaf(av.x, wv.x, av.y * wv.y);
                float p1 = fmaf(av.z, wv.z, av.w * wv.w);
                s[k] = p0 + p1;
            }
            #pragma unroll
            for (int d = 1; d <= 16; d <<= 1) {
                #pragma unroll
                for (int k = 0; k < 4; k++)
                    s[k] += __shfl_xor_sync(0xFFFFFFFF, s[k], d);
            }
            if (lane == 0) {
                #pragma unroll
                for (int k = 0; k < 4; k++) {
                    const int j = w + 8 * (g * 4 + k);
                    a2[j] = fmaxf(s[k] + b2[j], 0.f);
                }
            }
        }
    }
    __syncthreads();

    // Layer 3: 64 -> 3. Warps 0..2, one neuron each; lanes 0..15.
    if (w < OUT) {
        float s = 0.f;
        if (lane < 16) {
            const float4 wv = ((const float4*)(w3 + w * H2))[lane];
            const float4 av = ((const float4*)a2)[lane];
            s = fmaf(av.x, wv.x, fmaf(av.y, wv.y,
                fmaf(av.z, wv.z, av.w * wv.w)));
        }
        s += __shfl_xor_sync(0xFFFFFFFF, s, 1);
        s += __shfl_xor_sync(0xFFFFFFFF, s, 2);
        s += __shfl_xor_sync(0xFFFFFFFF, s, 4);
        s += __shfl_xor_sync(0xFFFFFFFF, s, 8);
        s += __shfl_xor_sync(0xFFFFFFFF, s, 16);
        if (lane == 0) out[b * OUT + w] = s + b3[w];
    }
}

extern "C" void kernel_launch(void* const* d_in, const int* in_sizes, int n_in,
                              void* d_out, int out_size) {
    const float* x     = (const float*)d_in[0];
    const float* w_ext = (const float*)d_in[1];
    const float* b_ext = (const float*)d_in[2];
    const float* w0    = (const float*)d_in[3];
    const float* b0    = (const float*)d_in[4];
    const float* w1    = (const float*)d_in[5];
    const float* b1    = (const float*)d_in[6];
    const float* w2    = (const float*)d_in[7];
    const float* b2    = (const float*)d_in[8];
    const float* w3    = (const float*)d_in[9];
    const float* b3    = (const float*)d_in[10];
    float* out = (float*)d_out;

    fused_kernel<<<B_SZ * CHUNKS, 256>>>(x, w_ext, b_ext, w0, b0, w1, b1,
                                         w2, b2, w3, b3, out);
}

// round 15
// speedup vs baseline: 1.0625x; 1.0625x over previous
#include <cuda_runtime.h>
#include <cuda_bf16.h>

// Problem constants (match reference)
#define B_SZ       128
#define S_SZ       4096
#define TOK        64          // token_dim
#define EFF        60          // token_dim - 4
#define NF         20          // num features
#define H0         256
#define H1         128
#define H2         64
#define OUT        3
#define CHUNKS     4
#define CHUNK_S    (S_SZ / CHUNKS)   // 1024 tokens per chunk
#define BPB        2                 // batches per MLP block
#define NT_MLP     512

// Scratch: partial column sums per (batch, chunk): [B, CHUNKS, TOK]
__device__ float g_partial[B_SZ * CHUNKS * TOK];

// ---------------------------------------------------------------------------
// Kernel 1: streaming column-sum — exact R1 geometry (512 blocks x 256
// threads, measured ~6.8 TB/s). NO weight prefetch (costs ~2us, gets
// flushed by the 134 MB stream anyway).
// ---------------------------------------------------------------------------
__global__ __launch_bounds__(256, 8)
void mean_sum_kernel(const float* __restrict__ x) {
    const int b = blockIdx.x >> 2;        // batch
    const int c = blockIdx.x & 3;         // chunk
    const int t = threadIdx.x;            // 0..255

    const float4* __restrict__ p =
        (const float4*)(x + ((size_t)b * S_SZ + (size_t)c * CHUNK_S) * TOK);

    // 16384 float4 per block; 64 per thread.
    float4 acc = make_float4(0.f, 0.f, 0.f, 0.f);
    #pragma unroll 16
    for (int i = t; i < CHUNK_S * (TOK / 4); i += 256) {
        float4 v = __ldcs(&p[i]);         // streaming: x touched once
        acc.x += v.x; acc.y += v.y; acc.z += v.z; acc.w += v.w;
    }

    __shared__ float4 sm[256];
    sm[t] = acc;
    __syncthreads();

    if (t < 16) {
        float4 s = make_float4(0.f, 0.f, 0.f, 0.f);
        #pragma unroll
        for (int k = 0; k < 16; k++) {
            float4 v = sm[t + k * 16];
            s.x += v.x; s.y += v.y; s.z += v.z; s.w += v.w;
        }
        float* dst = &g_partial[(size_t)(b * CHUNKS + c) * TOK + t * 4];
        dst[0] = s.x; dst[1] = s.y; dst[2] = s.z; dst[3] = s.w;
    }
}

// ---------------------------------------------------------------------------
// Kernel 2: MLP, 2 batches per block (64 blocks x 512 threads).
// Halves the L2 weight-multicast traffic (24 MB -> 12 MB); the second batch
// reuses the same weight registers/loads and its chains interleave with the
// first batch's (independent shfl-reduction chains pipeline).
// ---------------------------------------------------------------------------
__global__ __launch_bounds__(NT_MLP, 1)
void mlp_kernel(const float* __restrict__ w_ext, const float* __restrict__ b_ext,
                const float* __restrict__ w0, const float* __restrict__ b0,
                const float* __restrict__ w1, const float* __restrict__ b1,
                const float* __restrict__ w2, const float* __restrict__ b2,
                const float* __restrict__ w3, const float* __restrict__ b3,
                float* __restrict__ out) {
    const int base_b = blockIdx.x * BPB;
    const int t = threadIdx.x;            // 0..511
    const int w = t >> 5;                 // warp 0..15
    const int lane = t & 31;

    __shared__ float xm[BPB][TOK];
    __shared__ float feats[BPB][NF];
    __shared__ float a0[BPB][H0];
    __shared__ float a1[BPB][H1];
    __shared__ float a2[BPB][H2];

    // ---- Front-issued burst: this warp's 8 w1 rows + biases (64+8 regs) ---
    float4 w1a[8], w1b[8];
    float bias1[8];
    #pragma unroll
    for (int r = 0; r < 8; r++) {
        const int j = w + r * 16;
        const float4* wr = (const float4*)(w1 + j * H0);
        w1a[r] = wr[lane];
        w1b[r] = wr[lane + 32];
        bias1[r] = b1[j];
    }

    // ---- Combine chunk partials -> means for 2 batches (128 values) -------
    if (t < BPB * TOK) {
        const int bb = t >> 6;
        const int col = t & 63;
        const float* p0 = &g_partial[(size_t)((base_b + bb) * CHUNKS) * TOK + col];
        float s = (p0[0] + p0[TOK]) + (p0[2 * TOK] + p0[3 * TOK]);
        xm[bb][col] = s * (1.0f / (float)S_SZ);
    }
    __syncthreads();

    // ---- Extractor: 20 neurons x 2 batches. Warp w: j = w, w+16 (j<20). ---
    {
        float s[4];                        // chain (r, bb)
        float4 wv[2];
        wv[0] = make_float4(0.f, 0.f, 0.f, 0.f);
        wv[1] = make_float4(0.f, 0.f, 0.f, 0.f);
        if (lane < 15) {
            wv[0] = ((const float4*)(w_ext + w * EFF))[lane];
            if (w < 4)
                wv[1] = ((const float4*)(w_ext + (w + 16) * EFF))[lane];
        }
        #pragma unroll
        for (int r = 0; r < 2; r++) {
            #pragma unroll
            for (int bb = 0; bb < BPB; bb++) {
                float v = 0.f;
                if (lane < 15) {
                    const float4 av = ((const float4*)xm[bb])[lane];
                    v = fmaf(av.x, wv[r].x, fmaf(av.y, wv[r].y,
                        fmaf(av.z, wv[r].z, av.w * wv[r].w)));
                }
                s[r * BPB + bb] = v;
            }
        }
        #pragma unroll
        for (int d = 1; d <= 16; d <<= 1) {
            #pragma unroll
            for (int k = 0; k < 4; k++)
                s[k] += __shfl_xor_sync(0xFFFFFFFF, s[k], d);
        }
        if (lane == 0) {
            #pragma unroll
            for (int r = 0; r < 2; r++) {
                const int j = w + r * 16;
                if (j < NF) {
                    #pragma unroll
                    for (int bb = 0; bb < BPB; bb++)
                        feats[bb][j] = s[r * BPB + bb] + b_ext[j];
                }
            }
        }
    }
    __syncthreads();

    // ---- Layer 0: 20 -> 256 + ReLU. 512 tasks = 256 neurons x 2 batches ---
    {
        const int n = t & 255;
        const int bb = t >> 8;
        const float* __restrict__ wp = w0 + n * NF;
        float s0 = b0[n], s1 = 0.f;
        #pragma unroll
        for (int k = 0; k < NF; k += 2) {
            s0 = fmaf(feats[bb][k + 0], wp[k + 0], s0);
            s1 = fmaf(feats[bb][k + 1], wp[k + 1], s1);
        }
        a0[bb][n] = fmaxf(s0 + s1, 0.f);
    }
    __syncthreads();

    // ---- Layer 1: 256 -> 128 + ReLU. 16 interleaved chains (8 rounds x 2
    //      batches) from register-resident w1 rows. -------------------------
    {
        float4 av0[BPB], av1[BPB];
        #pragma unroll
        for (int bb = 0; bb < BPB; bb++) {
            const float4* ar = (const float4*)a0[bb];
            av0[bb] = ar[lane];
            av1[bb] = ar[lane + 32];
        }
        float s[16];
        #pragma unroll
        for (int r = 0; r < 8; r++) {
            #pragma unroll
            for (int bb = 0; bb < BPB; bb++) {
                float p0 = fmaf(av0[bb].x, w1a[r].x, av0[bb].y * w1a[r].y);
                float p1 = fmaf(av0[bb].z, w1a[r].z, av0[bb].w * w1a[r].w);
                float p2 = fmaf(av1[bb].x, w1b[r].x, av1[bb].y * w1b[r].y);
                float p3 = fmaf(av1[bb].z, w1b[r].z, av1[bb].w * w1b[r].w);
                s[r * BPB + bb] = (p0 + p1) + (p2 + p3);
            }
        }
        #pragma unroll
        for (int d = 1; d <= 16; d <<= 1) {
            #pragma unroll
            for (int k = 0; k < 16; k++)
                s[k] += __shfl_xor_sync(0xFFFFFFFF, s[k], d);
        }
        if (lane == 0) {
            #pragma unroll
            for (int r = 0; r < 8; r++) {
                const int j = w + r * 16;
                #pragma unroll
                for (int bb = 0; bb < BPB; bb++)
                    a1[bb][j] = fmaxf(s[r * BPB + bb] + bias1[r], 0.f);
            }
        }
    }
    __syncthreads();

    // ---- Layer 2: 128 -> 64 + ReLU. 8 interleaved chains (4 rounds x 2),
    //      w2 row loaded once per round, reused for both batches. -----------
    {
        float4 av[BPB];
        #pragma unroll
        for (int bb = 0; bb < BPB; bb++)
            av[bb] = ((const float4*)a1[bb])[lane];
        float s[8];
        float bias2[4];
        #pragma unroll
        for (int r = 0; r < 4; r++) {
            const int j = w + r * 16;
            const float4 wv = ((const float4*)(w2 + j * H1))[lane];
            bias2[r] = b2[j];
            #pragma unroll
            for (int bb = 0; bb < BPB; bb++) {
                float p0 = fmaf(av[bb].x, wv.x, av[bb].y * wv.y);
                float p1 = fmaf(av[bb].z, wv.z, av[bb].w * wv.w);
                s[r * BPB + bb] = p0 + p1;
            }
        }
        #pragma unroll
        for (int d = 1; d <= 16; d <<= 1) {
            #pragma unroll
            for (int k = 0; k < 8; k++)
                s[k] += __shfl_xor_sync(0xFFFFFFFF, s[k], d);
        }
        if (lane == 0) {
            #pragma unroll
            for (int r = 0; r < 4; r++) {
                const int j = w + r * 16;
                #pragma unroll
                for (int bb = 0; bb < BPB; bb++)
                    a2[bb][j] = fmaxf(s[r * BPB + bb] + bias2[r], 0.f);
            }
        }
    }
    __syncthreads();

    // ---- Layer 3: 64 -> 3 x 2 batches = 6 warps, one output each. ---------
    if (w < OUT * BPB) {
        const int j = w % OUT;
        const int bb = w / OUT;
        float s = 0.f;
        if (lane < 16) {
            const float4 wv = ((const float4*)(w3 + j * H2))[lane];
            const float4 av = ((const float4*)a2[bb])[lane];
            s = fmaf(av.x, wv.x, fmaf(av.y, wv.y,
                fmaf(av.z, wv.z, av.w * wv.w)));
        }
        s += __shfl_xor_sync(0xFFFFFFFF, s, 1);
        s += __shfl_xor_sync(0xFFFFFFFF, s, 2);
        s += __shfl_xor_sync(0xFFFFFFFF, s, 4);
        s += __shfl_xor_sync(0xFFFFFFFF, s, 8);
        s += __shfl_xor_sync(0xFFFFFFFF, s, 16);
        if (lane == 0) out[(base_b + bb) * OUT + j] = s + b3[j];
    }
}

extern "C" void kernel_launch(void* const* d_in, const int* in_sizes, int n_in,
                              void* d_out, int out_size) {
    const float* x     = (const float*)d_in[0];
    const float* w_ext = (const float*)d_in[1];
    const float* b_ext = (const float*)d_in[2];
    const float* w0    = (const float*)d_in[3];
    const float* b0    = (const float*)d_in[4];
    const float* w1    = (const float*)d_in[5];
    const float* b1    = (const float*)d_in[6];
    const float* w2    = (const float*)d_in[7];
    const float* b2    = (const float*)d_in[8];
    const float* w3    = (const float*)d_in[9];
    const float* b3    = (const float*)d_in[10];
    float* out = (float*)d_out;

    mean_sum_kernel<<<B_SZ * CHUNKS, 256>>>(x);
    mlp_kernel<<<B_SZ / BPB, NT_MLP>>>(w_ext, b_ext, w0, b0, w1, b1,
                                       w2, b2, w3, b3, out);
}

// round 17
// speedup vs baseline: 1.1333x; 1.0667x over previous
#include <cuda_runtime.h>
#include <cuda_bf16.h>

// Problem constants (match reference)
#define B_SZ       128
#define S_SZ       4096
#define TOK        64          // token_dim
#define EFF        60          // token_dim - 4
#define NF         20          // num features
#define H0         256
#define H1         128
#define H2         64
#define OUT        3
#define CHUNKS     4
#define CHUNK_S    (S_SZ / CHUNKS)   // 1024 tokens per chunk
#define NT_MLP     512

// Scratch: partial column sums per (batch, chunk): [B, CHUNKS, TOK]
__device__ float g_partial[B_SZ * CHUNKS * TOK];

// ---------------------------------------------------------------------------
// Kernel 1: streaming column-sum — exact R1 geometry (512 blocks x 256
// threads, measured ~6.8 TB/s). No weight prefetch (flushed by stream).
// ---------------------------------------------------------------------------
__global__ __launch_bounds__(256, 8)
void mean_sum_kernel(const float* __restrict__ x) {
    const int b = blockIdx.x >> 2;        // batch
    const int c = blockIdx.x & 3;         // chunk
    const int t = threadIdx.x;            // 0..255

    const float4* __restrict__ p =
        (const float4*)(x + ((size_t)b * S_SZ + (size_t)c * CHUNK_S) * TOK);

    // 16384 float4 per block; 64 per thread.
    float4 acc = make_float4(0.f, 0.f, 0.f, 0.f);
    #pragma unroll 16
    for (int i = t; i < CHUNK_S * (TOK / 4); i += 256) {
        float4 v = __ldcs(&p[i]);         // streaming: x touched once
        acc.x += v.x; acc.y += v.y; acc.z += v.z; acc.w += v.w;
    }

    __shared__ float4 sm[256];
    sm[t] = acc;
    __syncthreads();

    if (t < 16) {
        float4 s = make_float4(0.f, 0.f, 0.f, 0.f);
        #pragma unroll
        for (int k = 0; k < 16; k++) {
            float4 v = sm[t + k * 16];
            s.x += v.x; s.y += v.y; s.z += v.z; s.w += v.w;
        }
        float* dst = &g_partial[(size_t)(b * CHUNKS + c) * TOK + t * 4];
        dst[0] = s.x; dst[1] = s.y; dst[2] = s.z; dst[3] = s.w;
    }
}

// ---------------------------------------------------------------------------
// Kernel 2: per-batch MLP (128 blocks x 512 threads). ONE independent
// front-issued burst at entry loads: w1 rows -> registers (per warp),
// w_ext/w2/w3/biases -> ~42 KB static smem, and g_partial. After the burst,
// the only in-chain global access is w0 (layer 0). Everything else runs
// from registers/smem, so the serial stage chain is ~2 memory round trips.
// All float4-accessed shared arrays are explicitly 16B-aligned.
// ---------------------------------------------------------------------------
__global__ __launch_bounds__(NT_MLP, 1)
void mlp_kernel(const float* __restrict__ w_ext, const float* __restrict__ b_ext,
                const float* __restrict__ w0, const float* __restrict__ b0,
                const float* __restrict__ w1, const float* __restrict__ b1,
                const float* __restrict__ w2, const float* __restrict__ b2,
                const float* __restrict__ w3, const float* __restrict__ b3,
                float* __restrict__ out) {
    const int b = blockIdx.x;
    const int t = threadIdx.x;            // 0..511
    const int w = t >> 5;                 // warp 0..15
    const int lane = t & 31;

    __shared__ __align__(16) float s_wext[NF * EFF];   // 4.8 KB (1200 f)
    __shared__ __align__(16) float s_w2[H2 * H1];      // 32 KB
    __shared__ __align__(16) float s_w3[OUT * H2];     // 768 B (192 f)
    __shared__ __align__(16) float s_b0[H0];
    __shared__ __align__(16) float s_bext[NF];         // 20 f (mult of 4)
    __shared__ __align__(16) float s_b2[H2];
    __shared__ __align__(16) float s_b3[4];            // padded from 3
    __shared__ __align__(16) float xm[TOK];
    __shared__ __align__(16) float feats[NF];          // 20 f (mult of 4)
    __shared__ __align__(16) float a0[H0];
    __shared__ __align__(16) float a1[H1];
    __shared__ __align__(16) float a2[H2];

    // ================= Front-issued independent load burst =================
    // (1) g_partial combine loads (4 per thread for t < 64)
    float gp0 = 0.f, gp1 = 0.f, gp2 = 0.f, gp3 = 0.f;
    if (t < TOK) {
        const float* p0 = &g_partial[(size_t)(b * CHUNKS) * TOK + t];
        gp0 = p0[0]; gp1 = p0[TOK]; gp2 = p0[2 * TOK]; gp3 = p0[3 * TOK];
    }
    // (2) w1 rows + b1 for this warp's 8 neurons -> registers (72 regs)
    float4 w1a[8], w1b[8];
    float bias1[8];
    #pragma unroll
    for (int r = 0; r < 8; r++) {
        const int j = w + r * 16;
        const float4* wr = (const float4*)(w1 + j * H0);
        w1a[r] = wr[lane];
        w1b[r] = wr[lane + 32];
        bias1[r] = b1[j];
    }
    // (3) w_ext, w2, w3, biases -> smem (coalesced cooperative copies)
    {
        #pragma unroll 4
        for (int i = t; i < (H2 * H1) / 4; i += NT_MLP)        // 2048 f4
            ((float4*)s_w2)[i] = ((const float4*)w2)[i];
        if (t < (NF * EFF) / 4)                                // 300 f4
            ((float4*)s_wext)[t] = ((const float4*)w_ext)[t];
        if (t < (OUT * H2) / 4)                                // 48 f4
            ((float4*)s_w3)[t] = ((const float4*)w3)[t];
        if (t < H0)  s_b0[t] = b0[t];
        if (t < NF)  s_bext[t] = b_ext[t];
        if (t < H2)  s_b2[t] = b2[t];
        if (t < OUT) s_b3[t] = b3[t];
    }
    // Finish the mean
    if (t < TOK)
        xm[t] = ((gp0 + gp1) + (gp2 + gp3)) * (1.0f / (float)S_SZ);
    __syncthreads();
    // =======================================================================

    // ---- Extractor: thread-per-neuron (t < 20), all operands in smem ------
    if (t < NF) {
        const float* wp = s_wext + t * EFF;
        float s0 = s_bext[t], s1 = 0.f, s2 = 0.f, s3 = 0.f;
        #pragma unroll
        for (int k = 0; k < EFF; k += 4) {
            s0 = fmaf(xm[k + 0], wp[k + 0], s0);
            s1 = fmaf(xm[k + 1], wp[k + 1], s1);
            s2 = fmaf(xm[k + 2], wp[k + 2], s2);
            s3 = fmaf(xm[k + 3], wp[k + 3], s3);
        }
        feats[t] = (s0 + s1) + (s2 + s3);
    }
    __syncthreads();

    // ---- Layer 0: 20 -> 256 + ReLU. One neuron per thread (t < 256).
    //      w0 row = 80 B (16B-aligned); 5 independent float4 loads,
    //      front-issued — the ONLY in-chain global access. ------------------
    if (t < H0) {
        const float4* __restrict__ wp = (const float4*)(w0 + t * NF);
        float4 wv0 = wp[0], wv1 = wp[1], wv2 = wp[2], wv3 = wp[3], wv4 = wp[4];
        float s0 = s_b0[t], s1 = 0.f, s2 = 0.f, s3 = 0.f;
        s0 = fmaf(feats[0],  wv0.x, s0); s1 = fmaf(feats[1],  wv0.y, s1);
        s2 = fmaf(feats[2],  wv0.z, s2); s3 = fmaf(feats[3],  wv0.w, s3);
        s0 = fmaf(feats[4],  wv1.x, s0); s1 = fmaf(feats[5],  wv1.y, s1);
        s2 = fmaf(feats[6],  wv1.z, s2); s3 = fmaf(feats[7],  wv1.w, s3);
        s0 = fmaf(feats[8],  wv2.x, s0); s1 = fmaf(feats[9],  wv2.y, s1);
        s2 = fmaf(feats[10], wv2.z, s2); s3 = fmaf(feats[11], wv2.w, s3);
        s0 = fmaf(feats[12], wv3.x, s0); s1 = fmaf(feats[13], wv3.y, s1);
        s2 = fmaf(feats[14], wv3.z, s2); s3 = fmaf(feats[15], wv3.w, s3);
        s0 = fmaf(feats[16], wv4.x, s0); s1 = fmaf(feats[17], wv4.y, s1);
        s2 = fmaf(feats[18], wv4.z, s2); s3 = fmaf(feats[19], wv4.w, s3);
        a0[t] = fmaxf((s0 + s1) + (s2 + s3), 0.f);
    }
    __syncthreads();

    // ---- Layer 1: 256 -> 128 + ReLU. Weights in registers; 8 independent
    //      partials then interleaved shfl-reduction chains. ----------------
    {
        const float4* ar = (const float4*)a0;
        const float4 a0v = ar[lane];
        const float4 a1v = ar[lane + 32];
        float s[8];
        #pragma unroll
        for (int r = 0; r < 8; r++) {
            float p0 = fmaf(a0v.x, w1a[r].x, a0v.y * w1a[r].y);
            float p1 = fmaf(a0v.z, w1a[r].z, a0v.w * w1a[r].w);
            float p2 = fmaf(a1v.x, w1b[r].x, a1v.y * w1b[r].y);
            float p3 = fmaf(a1v.z, w1b[r].z, a1v.w * w1b[r].w);
            s[r] = (p0 + p1) + (p2 + p3);
        }
        #pragma unroll
        for (int d = 1; d <= 16; d <<= 1) {
            #pragma unroll
            for (int r = 0; r < 8; r++)
                s[r] += __shfl_xor_sync(0xFFFFFFFF, s[r], d);
        }
        if (lane == 0) {
            #pragma unroll
            for (int r = 0; r < 8; r++)
                a1[w + r * 16] = fmaxf(s[r] + bias1[r], 0.f);
        }
    }
    __syncthreads();

    // ---- Layer 2: 128 -> 64 + ReLU. Weights in smem; interleaved chains. --
    {
        const float4 av = ((const float4*)a1)[lane];
        float s[4];
        float bb2[4];
        #pragma unroll
        for (int r = 0; r < 4; r++) {
            const int j = w + r * 16;
            const float4 wv = ((const float4*)(s_w2 + j * H1))[lane];
            bb2[r] = s_b2[j];
            float p0 = fmaf(av.x, wv.x, av.y * wv.y);
            float p1 = fmaf(av.z, wv.z, av.w * wv.w);
            s[r] = p0 + p1;
        }
        #pragma unroll
        for (int d = 1; d <= 16; d <<= 1) {
            #pragma unroll
            for (int r = 0; r < 4; r++)
                s[r] += __shfl_xor_sync(0xFFFFFFFF, s[r], d);
        }
        if (lane == 0) {
            #pragma unroll
            for (int r = 0; r < 4; r++)
                a2[w + r * 16] = fmaxf(s[r] + bb2[r], 0.f);
        }
    }
    __syncthreads();

    // ---- Layer 3: 64 -> 3 from smem. Warps 0..2, one neuron each. ---------
    if (w < OUT) {
        float s = 0.f;
        if (lane < 16) {
            const float4 wv = ((const float4*)(s_w3 + w * H2))[lane];
            const float4 av = ((const float4*)a2)[lane];
            s = fmaf(av.x, wv.x, fmaf(av.y, wv.y,
                fmaf(av.z, wv.z, av.w * wv.w)));
        }
        s += __shfl_xor_sync(0xFFFFFFFF, s, 1);
        s += __shfl_xor_sync(0xFFFFFFFF, s, 2);
        s += __shfl_xor_sync(0xFFFFFFFF, s, 4);
        s += __shfl_xor_sync(0xFFFFFFFF, s, 8);
        s += __shfl_xor_sync(0xFFFFFFFF, s, 16);
        if (lane == 0) out[b * OUT + w] = s + s_b3[w];
    }
}

extern "C" void kernel_launch(void* const* d_in, const int* in_sizes, int n_in,
                              void* d_out, int out_size) {
    const float* x     = (const float*)d_in[0];
    const float* w_ext = (const float*)d_in[1];
    const float* b_ext = (const float*)d_in[2];
    const float* w0    = (const float*)d_in[3];
    const float* b0    = (const float*)d_in[4];
    const float* w1    = (const float*)d_in[5];
    const float* b1    = (const float*)d_in[6];
    const float* w2    = (const float*)d_in[7];
    const float* b2    = (const float*)d_in[8];
    const float* w3    = (const float*)d_in[9];
    const float* b3    = (const float*)d_in[10];
    float* out = (float*)d_out;

    mean_sum_kernel<<<B_SZ * CHUNKS, 256>>>(x);
    mlp_kernel<<<B_SZ, NT_MLP>>>(w_ext, b_ext, w0, b0, w1, b1,
                                 w2, b2, w3, b3, out);
}